// round 8
// baseline (speedup 1.0000x reference)
#include <cuda_runtime.h>
#include <cstdint>

// FWHT, 4096 rows x 16384 fp32. Persistent, 2 CTAs/SM (grid=296), 1024 thr,
// <=32 regs (launch_bounds(1024,2)) for 64-warp occupancy, PLUS prefetch via
// cp.async.bulk (register-free): first half of next row staged into smem with
// an mbarrier; second half loaded direct (LDG.128, hidden by TLP).
// Per-row dataflow (R5, MIO-minimal for this shape):
//   P1: regs H16 over bits {13,12,1,0}  (half from staging, half from gmem)
//   X1 -> P2: regs H16 over bits {11..8}  (same-address writeback)
//   X2 -> P3: regs H16 over bits {7..4}
//   shfl stages over bits {3,2}; scale; coalesced STG.  3 barriers/row.
// Work-buffer swizzle phys(i) = i + 16*(i>>8): injective, 16B-aligned,
// conflict-free for all four patterns (verified R5/R6/R7).

#define N_ELEM 16384
#define THREADS 1024
#define STAGE_FLOATS 8192            // first half of a row, 32768 bytes
#define WORK_FLOATS 17408            // max phys idx 16383 + 16*63 = 17391
#define WORK_OFF STAGE_FLOATS        // staging at 0 (16B aligned), work after
#define MBAR_OFF (WORK_OFF + WORK_FLOATS)  // float index; byte off 102400, 8-aligned
#define SMEM_BYTES ((MBAR_OFF + 4) * 4)
#define GRID 296

__device__ __forceinline__ int physz(int i) { return i + ((i >> 8) << 4); }

template <int N>
__device__ __forceinline__ void hadN(float* v) {
#pragma unroll
    for (int s = 1; s < N; s <<= 1) {
#pragma unroll
        for (int i = 0; i < N; i++) {
            if ((i & s) == 0) {
                float a = v[i];
                float b = v[i | s];
                v[i]     = a + b;
                v[i | s] = a - b;
            }
        }
    }
}

__device__ __forceinline__ void bulk_prefetch(uint32_t stag_u32, const float* src,
                                              uint32_t mbar_u32) {
    // expect_tx arrive (count-1 barrier) + bulk copy of 32KB
    asm volatile(
        "mbarrier.arrive.expect_tx.shared::cta.b64 _, [%0], %1;"
        :: "r"(mbar_u32), "r"((uint32_t)(STAGE_FLOATS * 4)) : "memory");
    asm volatile(
        "cp.async.bulk.shared::cta.global.mbarrier::complete_tx::bytes "
        "[%0], [%1], %2, [%3];"
        :: "r"(stag_u32), "l"((const void*)src),
           "r"((uint32_t)(STAGE_FLOATS * 4)), "r"(mbar_u32) : "memory");
}

__device__ __forceinline__ void mbar_wait(uint32_t mbar_u32, uint32_t parity) {
    asm volatile(
        "{\n\t.reg .pred P;\n"
        "W%=:\n\t"
        "mbarrier.try_wait.parity.shared::cta.b64 P, [%0], %1;\n\t"
        "@!P bra W%=;\n\t}"
        :: "r"(mbar_u32), "r"(parity) : "memory");
}

__global__ __launch_bounds__(THREADS, 2)
void fwht_kernel(const float* __restrict__ in, float* __restrict__ out,
                 int nrows) {
    extern __shared__ float sh[];
    const int t = threadIdx.x;
    const int l = t & 31;
    float* __restrict__ stag = sh;
    float* __restrict__ work = sh + WORK_OFF;

    const uint32_t stag_u32 = (uint32_t)__cvta_generic_to_shared(stag);
    const uint32_t mbar_u32 = (uint32_t)__cvta_generic_to_shared(sh + MBAR_OFF);

    // bases (fold to immediates in the unrolled loops)
    const int pa  = (t << 2) + ((t >> 6) << 4);          // phys(t<<2)
    const int pb1 = physz(((t >> 8) << 12) | (t & 255)); // X1 pattern base
    const int b2  = ((t >> 4) << 8) | (t & 15);
    const int pb2 = physz(b2);

    const float s3 = (l & 8) ? -1.0f : 1.0f;
    const float s2 = (l & 4) ? -1.0f : 1.0f;

    // ---- prologue: init mbarrier, kick off staging of first row's first half
    if (t == 0) {
        asm volatile("mbarrier.init.shared::cta.b64 [%0], 1;"
                     :: "r"(mbar_u32) : "memory");
    }
    __syncthreads();
    int row = blockIdx.x;
    if (t == 0) bulk_prefetch(stag_u32, in + (size_t)row * N_ELEM, mbar_u32);

    uint32_t parity = 0;
    while (row < nrows) {
        const int nextrow = row + GRID;

        // ---- wait for staged first half of this row
        mbar_wait(mbar_u32, parity);
        parity ^= 1;

        float v[16];
        // P1 loads: j=0,1 from staging (LDS.128), j=2,3 direct (LDG.128)
#pragma unroll
        for (int j = 0; j < 2; j++) {
            float4 f = *reinterpret_cast<const float4*>(&stag[(j << 12) + (t << 2)]);
            v[4 * j + 0] = f.x; v[4 * j + 1] = f.y;
            v[4 * j + 2] = f.z; v[4 * j + 3] = f.w;
        }
        const float4* __restrict__ pin4 =
            reinterpret_cast<const float4*>(in + (size_t)row * N_ELEM + (t << 2));
#pragma unroll
        for (int j = 2; j < 4; j++) {
            float4 f = pin4[(size_t)j << 10];
            v[4 * j + 0] = f.x; v[4 * j + 1] = f.y;
            v[4 * j + 2] = f.z; v[4 * j + 3] = f.w;
        }
        hadN<16>(v);  // butterflies bits {13,12,1,0}

        // B1: staging reads done (WAR for next bulk) AND previous row's
        //     X2-reads of the work buffer done (WAR for X1 writes below).
        __syncthreads();
        if (t == 0 && nextrow < nrows)
            bulk_prefetch(stag_u32, in + (size_t)nextrow * N_ELEM, mbar_u32);

        // ---- X1 write: STS.128 into work
#pragma unroll
        for (int j = 0; j < 4; j++) {
            *reinterpret_cast<float4*>(&work[pa + j * 4352]) =
                make_float4(v[4 * j + 0], v[4 * j + 1], v[4 * j + 2], v[4 * j + 3]);
        }
        __syncthreads();  // B2

        // ---- P2: bits {11..8}; in-place writeback
#pragma unroll
        for (int r = 0; r < 16; r++) v[r] = work[pb1 + r * 272];
        hadN<16>(v);
#pragma unroll
        for (int r = 0; r < 16; r++) work[pb1 + r * 272] = v[r];
        __syncthreads();  // B3

        // ---- P3: bits {7..4}
#pragma unroll
        for (int r = 0; r < 16; r++) v[r] = work[pb2 + r * 16];
        hadN<16>(v);

        // ---- bits {3,2} on lane bits 3,2 via shfl-xor sign trick
#pragma unroll
        for (int r = 0; r < 16; r++) {
            float q = __shfl_xor_sync(0xffffffffu, v[r], 8);
            v[r] = fmaf(s3, v[r], q);
        }
#pragma unroll
        for (int r = 0; r < 16; r++) {
            float q = __shfl_xor_sync(0xffffffffu, v[r], 4);
            v[r] = fmaf(s2, v[r], q);
        }

        // ---- scale 2^-7, coalesced store
        float* __restrict__ pout = out + (size_t)row * N_ELEM;
#pragma unroll
        for (int r = 0; r < 16; r++)
            pout[b2 + (r << 4)] = v[r] * 0.0078125f;

        row = nextrow;
    }
}

extern "C" void kernel_launch(void* const* d_in, const int* in_sizes, int n_in,
                              void* d_out, int out_size) {
    const float* phi = (const float*)d_in[0];
    float* out = (float*)d_out;

    cudaFuncSetAttribute(fwht_kernel,
                         cudaFuncAttributeMaxDynamicSharedMemorySize,
                         SMEM_BYTES);

    const int nrows = in_sizes[0] / N_ELEM;  // 4096
    const int grid = nrows < GRID ? nrows : GRID;
    fwht_kernel<<<grid, THREADS, SMEM_BYTES>>>(phi, out, nrows);
}